// round 1
// baseline (speedup 1.0000x reference)
#include <cuda_runtime.h>
#include <math.h>

#define NN   50000
#define EE   800000
#define IN_F 30
#define HH   8
#define DD   32
#define GG   512
#define HIDN 128
#define F1   256            // H*D

// ---------------- device scratch (no allocation allowed) ----------------
__device__ float g_feat1[NN * F1];
__device__ float g_out1 [NN * F1];
__device__ float g_h1   [NN * F1];
__device__ float g_feat2[NN * F1];
__device__ float g_out2 [NN * F1];
__device__ float g_el1[NN * HH], g_er1[NN * HH], g_m1[NN * HH], g_s1[NN * HH];
__device__ float g_el2[NN * HH], g_er2[NN * HH], g_m2[NN * HH], g_s2[NN * HH];
__device__ float g_e[(size_t)EE * HH];
__device__ float g_gsum[GG * DD], g_gmax[GG * DD];

// float atomic max via int/uint ordering trick (init must be -inf)
__device__ __forceinline__ void atomicMaxF(float* addr, float v) {
    if (v >= 0.0f) atomicMax((int*)addr, __float_as_int(v));
    else           atomicMin((unsigned int*)addr, __float_as_uint(v));
}

// ---------------- Stage A: layer-1 projection + attention dots + inits ----
__global__ void __launch_bounds__(256) kA(
    const float* __restrict__ x, const float* __restrict__ W1,
    const float* __restrict__ resW1, const float* __restrict__ b1,
    const float* __restrict__ al1, const float* __restrict__ ar1)
{
    int n = blockIdx.x;
    int t = threadIdx.x;
    __shared__ float xs[IN_F];
    if (t < IN_F) xs[t] = x[n * IN_F + t];
    __syncthreads();

    float f = 0.f, r = 0.f;
#pragma unroll
    for (int k = 0; k < IN_F; k++) {
        float xv = xs[k];
        f += xv * W1[k * F1 + t];
        r += xv * resW1[k * F1 + t];
    }
    g_feat1[n * F1 + t] = f;
    g_out1[n * F1 + t]  = r + b1[t];   // residual + bias pre-seeded

    int h = t >> 5, lane = t & 31;
    float elv = f * al1[h * DD + lane];
    float erv = f * ar1[h * DD + lane];
#pragma unroll
    for (int o = 16; o > 0; o >>= 1) {
        elv += __shfl_down_sync(0xffffffffu, elv, o);
        erv += __shfl_down_sync(0xffffffffu, erv, o);
    }
    if (lane == 0) { g_el1[n * HH + h] = elv; g_er1[n * HH + h] = erv; }
    if (t < HH)    { g_m1[n * HH + t] = -INFINITY; g_s1[n * HH + t] = 0.f; }

    int gid = n * F1 + t;
    if (gid < GG * DD) { g_gsum[gid] = 0.f; g_gmax[gid] = -INFINITY; }
}

// ---------------- Edge pass 1: e = leaky(el[src]+er[dst]), segment max ----
__global__ void __launch_bounds__(256) kEdgeMax(
    const int* __restrict__ src, const int* __restrict__ dst, int layer)
{
    int e = blockIdx.x * blockDim.x + threadIdx.x;
    if (e >= EE) return;
    const float* el = layer ? g_el2 : g_el1;
    const float* er = layer ? g_er2 : g_er1;
    float* mb       = layer ? g_m2  : g_m1;
    int s = src[e], d = dst[e];
    float4 a0 = *(const float4*)(el + s * HH);
    float4 a1 = *(const float4*)(el + s * HH + 4);
    float4 b0 = *(const float4*)(er + d * HH);
    float4 b1 = *(const float4*)(er + d * HH + 4);
    float v[8] = { a0.x + b0.x, a0.y + b0.y, a0.z + b0.z, a0.w + b0.w,
                   a1.x + b1.x, a1.y + b1.y, a1.z + b1.z, a1.w + b1.w };
#pragma unroll
    for (int h = 0; h < 8; h++) {
        float vv = v[h];
        vv = vv > 0.f ? vv : 0.2f * vv;
        vv = vv + 0.0f;               // canonicalize -0 for int-trick atomics
        v[h] = vv;
        atomicMaxF(&mb[d * HH + h], vv);
    }
    *(float4*)(g_e + (size_t)e * 8)     = make_float4(v[0], v[1], v[2], v[3]);
    *(float4*)(g_e + (size_t)e * 8 + 4) = make_float4(v[4], v[5], v[6], v[7]);
}

// ---------------- Edge pass 2: ex = exp(e - m[dst]), segment sum ----------
__global__ void __launch_bounds__(256) kEdgeExp(
    const int* __restrict__ dst, int layer)
{
    int e = blockIdx.x * blockDim.x + threadIdx.x;
    if (e >= EE) return;
    const float* mb = layer ? g_m2 : g_m1;
    float* sb       = layer ? g_s2 : g_s1;
    int d = dst[e];
    float4 m0 = *(const float4*)(mb + d * HH);
    float4 m1 = *(const float4*)(mb + d * HH + 4);
    float4 e0 = *(float4*)(g_e + (size_t)e * 8);
    float4 e1 = *(float4*)(g_e + (size_t)e * 8 + 4);
    float ex[8];
    ex[0] = expf(e0.x - m0.x); ex[1] = expf(e0.y - m0.y);
    ex[2] = expf(e0.z - m0.z); ex[3] = expf(e0.w - m0.w);
    ex[4] = expf(e1.x - m1.x); ex[5] = expf(e1.y - m1.y);
    ex[6] = expf(e1.z - m1.z); ex[7] = expf(e1.w - m1.w);
    *(float4*)(g_e + (size_t)e * 8)     = make_float4(ex[0], ex[1], ex[2], ex[3]);
    *(float4*)(g_e + (size_t)e * 8 + 4) = make_float4(ex[4], ex[5], ex[6], ex[7]);
#pragma unroll
    for (int h = 0; h < 8; h++) atomicAdd(&sb[d * HH + h], ex[h]);
}

// ---------------- Edge pass 3: out[dst] += a * feat[src] (warp/edge) ------
__global__ void __launch_bounds__(256) kEdgeAgg(
    const int* __restrict__ src, const int* __restrict__ dst, int layer)
{
    int e = blockIdx.x * 8 + (threadIdx.x >> 5);
    int lane = threadIdx.x & 31;
    if (e >= EE) return;
    const float* feat = layer ? g_feat2 : g_feat1;
    const float* sb   = layer ? g_s2    : g_s1;
    float* out        = layer ? g_out2  : g_out1;
    int s = src[e], d = dst[e];
    float a = 0.f;
    if (lane < 8) {
        float exv = g_e[(size_t)e * 8 + lane];
        float sv  = sb[d * HH + lane];
        a = exv / fmaxf(sv, 1e-9f);
    }
#pragma unroll
    for (int r2 = 0; r2 < 2; r2++) {
        int idx = r2 * 128 + lane * 4;
        int h   = idx >> 5;
        float av = __shfl_sync(0xffffffffu, a, h);
        float4 fv = *(const float4*)(feat + (size_t)s * F1 + idx);
        float* p  = out + (size_t)d * F1 + idx;
        asm volatile("red.global.add.v4.f32 [%0], {%1,%2,%3,%4};"
                     :: "l"(p), "f"(av * fv.x), "f"(av * fv.y),
                        "f"(av * fv.z), "f"(av * fv.w) : "memory");
    }
}

// ---------------- Stage E: ELU -> h1, seed out2 = b2 + h1, init l2 bufs ---
__global__ void __launch_bounds__(256) kE(const float* __restrict__ b2)
{
    int n = blockIdx.x, t = threadIdx.x;
    float v = g_out1[n * F1 + t];
    float h1 = v > 0.f ? v : expm1f(v);
    g_h1[n * F1 + t]   = h1;
    g_out2[n * F1 + t] = b2[t] + h1;
    if (t < HH) { g_m2[n * HH + t] = -INFINITY; g_s2[n * HH + t] = 0.f; }
}

// ---------------- Stage F: feat2 = h1 @ W2  (N x 256 x 256) ---------------
__global__ void __launch_bounds__(256) kGemm2(const float* __restrict__ W2)
{
    __shared__ float hs[32][F1];
    int row0 = blockIdx.x * 32;
    int rows = NN - row0; if (rows > 32) rows = 32;

    for (int i = threadIdx.x; i < 32 * 64; i += 256) {
        int r = i >> 6, c4 = i & 63;
        float4 v = (r < rows) ? ((const float4*)(g_h1 + (size_t)(row0 + r) * F1))[c4]
                              : make_float4(0.f, 0.f, 0.f, 0.f);
        ((float4*)&hs[r][0])[c4] = v;
    }
    __syncthreads();

    int cg = threadIdx.x & 63;   // 4-col group
    int rg = threadIdx.x >> 6;   // 8-row group
    float acc[8][4];
#pragma unroll
    for (int i = 0; i < 8; i++) { acc[i][0] = acc[i][1] = acc[i][2] = acc[i][3] = 0.f; }

    const float4* W2v = (const float4*)W2;
#pragma unroll 4
    for (int k = 0; k < F1; k++) {
        float4 w = W2v[k * 64 + cg];
#pragma unroll
        for (int i = 0; i < 8; i++) {
            float xv = hs[rg * 8 + i][k];
            acc[i][0] += xv * w.x; acc[i][1] += xv * w.y;
            acc[i][2] += xv * w.z; acc[i][3] += xv * w.w;
        }
    }
#pragma unroll
    for (int i = 0; i < 8; i++) {
        int r = rg * 8 + i;
        if (r < rows)
            ((float4*)(g_feat2 + (size_t)(row0 + r) * F1))[cg] =
                make_float4(acc[i][0], acc[i][1], acc[i][2], acc[i][3]);
    }
}

// ---------------- Stage F2: layer-2 attention dots ------------------------
__global__ void __launch_bounds__(256) kPrep2(
    const float* __restrict__ al2, const float* __restrict__ ar2)
{
    int n = blockIdx.x, t = threadIdx.x;
    float f = g_feat2[n * F1 + t];
    int h = t >> 5, lane = t & 31;
    float elv = f * al2[h * DD + lane];
    float erv = f * ar2[h * DD + lane];
#pragma unroll
    for (int o = 16; o > 0; o >>= 1) {
        elv += __shfl_down_sync(0xffffffffu, elv, o);
        erv += __shfl_down_sync(0xffffffffu, erv, o);
    }
    if (lane == 0) { g_el2[n * HH + h] = elv; g_er2[n * HH + h] = erv; }
}

// ---------------- Stage G: head mean, gate, graph readout atomics ---------
__global__ void __launch_bounds__(256) kG(
    const int* __restrict__ gids, const float* __restrict__ Ww,
    const float* __restrict__ bw)
{
    int n = blockIdx.x * 8 + (threadIdx.x >> 5);
    int d = threadIdx.x & 31;
    if (n >= NN) return;
    float acc = 0.f;
#pragma unroll
    for (int h = 0; h < HH; h++) acc += g_out2[(size_t)n * F1 + h * DD + d];
    float h2 = acc * 0.125f;                     // mean over heads
    float wv = h2 * Ww[d];
#pragma unroll
    for (int o = 16; o > 0; o >>= 1) wv += __shfl_xor_sync(0xffffffffu, wv, o);
    float w = 1.f / (1.f + expf(-(wv + bw[0])));
    int g = gids[n];
    atomicAdd(&g_gsum[g * DD + d], w * h2);
    atomicMaxF(&g_gmax[g * DD + d], h2);
}

// ---------------- Stage H: MLP predictor ----------------------------------
__global__ void __launch_bounds__(128) kH(
    const float* __restrict__ Wp1, const float* __restrict__ bp1,
    const float* __restrict__ gamma, const float* __restrict__ beta,
    const float* __restrict__ rm, const float* __restrict__ rv,
    const float* __restrict__ Wp2, const float* __restrict__ bp2,
    float* __restrict__ outp)
{
    int g = blockIdx.x, t = threadIdx.x;
    __shared__ float gs[64];
    __shared__ float wsum[4];
    if (t < 32) gs[t] = g_gsum[g * DD + t];
    else if (t < 64) {
        float mv = g_gmax[g * DD + (t - 32)];
        if (!isfinite(mv)) mv = 0.f;
        gs[t] = mv;
    }
    __syncthreads();
    float acc = bp1[t];
#pragma unroll
    for (int k = 0; k < 64; k++) acc += gs[k] * Wp1[k * HIDN + t];
    acc = fmaxf(acc, 0.f);
    acc = (acc - rm[t]) * rsqrtf(rv[t] + 1e-5f) * gamma[t] + beta[t];
    float v = acc * Wp2[t];
#pragma unroll
    for (int o = 16; o > 0; o >>= 1) v += __shfl_xor_sync(0xffffffffu, v, o);
    if ((t & 31) == 0) wsum[t >> 5] = v;
    __syncthreads();
    if (t == 0) outp[g] = wsum[0] + wsum[1] + wsum[2] + wsum[3] + bp2[0];
}

// ---------------- launcher ------------------------------------------------
extern "C" void kernel_launch(void* const* d_in, const int* in_sizes, int n_in,
                              void* d_out, int out_size)
{
    const float* x     = (const float*)d_in[0];
    const int*   src   = (const int*)  d_in[1];
    const int*   dst   = (const int*)  d_in[2];
    const int*   gids  = (const int*)  d_in[3];
    const float* W1    = (const float*)d_in[4];
    const float* al1   = (const float*)d_in[5];
    const float* ar1   = (const float*)d_in[6];
    const float* b1    = (const float*)d_in[7];
    const float* resW1 = (const float*)d_in[8];
    const float* W2    = (const float*)d_in[9];
    const float* al2   = (const float*)d_in[10];
    const float* ar2   = (const float*)d_in[11];
    const float* b2    = (const float*)d_in[12];
    const float* Ww    = (const float*)d_in[13];
    const float* bw    = (const float*)d_in[14];
    const float* Wp1   = (const float*)d_in[15];
    const float* bp1   = (const float*)d_in[16];
    const float* gamma = (const float*)d_in[17];
    const float* beta  = (const float*)d_in[18];
    const float* rm    = (const float*)d_in[19];
    const float* rv    = (const float*)d_in[20];
    const float* Wp2   = (const float*)d_in[21];
    const float* bp2   = (const float*)d_in[22];
    float* outp = (float*)d_out;

    int eb = (EE + 255) / 256;

    kA<<<NN, 256>>>(x, W1, resW1, b1, al1, ar1);
    kEdgeMax<<<eb, 256>>>(src, dst, 0);
    kEdgeExp<<<eb, 256>>>(dst, 0);
    kEdgeAgg<<<(EE + 7) / 8, 256>>>(src, dst, 0);
    kE<<<NN, 256>>>(b2);
    kGemm2<<<(NN + 31) / 32, 256>>>(W2);
    kPrep2<<<NN, 256>>>(al2, ar2);
    kEdgeMax<<<eb, 256>>>(src, dst, 1);
    kEdgeExp<<<eb, 256>>>(dst, 1);
    kEdgeAgg<<<(EE + 7) / 8, 256>>>(src, dst, 1);
    kG<<<(NN + 7) / 8, 256>>>(gids, Ww, bw);
    kH<<<GG, 128>>>(Wp1, bp1, gamma, beta, rm, rv, Wp2, bp2, outp);
}

// round 2
// speedup vs baseline: 1.0204x; 1.0204x over previous
#include <cuda_runtime.h>
#include <math.h>

#define NN   50000
#define EE   800000
#define IN_F 30
#define HH   8
#define DD   32
#define GG   512
#define HIDN 128
#define F1   256            // H*D

// ---------------- device scratch (no allocation allowed) ----------------
__device__ float g_feat1[NN * F1];
__device__ float g_out1 [NN * F1];   // layer-1 seed: x@resW1 + b1
__device__ float g_h1   [NN * F1];
__device__ float g_feat2[NN * F1];
__device__ float g_el1[NN * HH], g_er1[NN * HH];
__device__ float g_el2[NN * HH], g_er2[NN * HH];
__device__ float g_gsum[GG * DD], g_gmax[GG * DD];
// CSR-by-dst
__device__ int g_cnt[NN];
__device__ int g_rowptr[NN + 1];
__device__ int g_cursor[NN];
__device__ int g_csrc[EE];

__device__ __forceinline__ void atomicMaxF(float* addr, float v) {
    if (v >= 0.0f) atomicMax((int*)addr, __float_as_int(v));
    else           atomicMin((unsigned int*)addr, __float_as_uint(v));
}

// ---------------- Stage A: layer-1 projection + attention dots + inits ----
__global__ void __launch_bounds__(256) kA(
    const float* __restrict__ x, const float* __restrict__ W1,
    const float* __restrict__ resW1, const float* __restrict__ b1,
    const float* __restrict__ al1, const float* __restrict__ ar1)
{
    int n = blockIdx.x;
    int t = threadIdx.x;
    __shared__ float xs[IN_F];
    if (t < IN_F) xs[t] = x[n * IN_F + t];
    if (t == 0) g_cnt[n] = 0;
    __syncthreads();

    float f = 0.f, r = 0.f;
#pragma unroll
    for (int k = 0; k < IN_F; k++) {
        float xv = xs[k];
        f += xv * W1[k * F1 + t];
        r += xv * resW1[k * F1 + t];
    }
    g_feat1[n * F1 + t] = f;
    g_out1[n * F1 + t]  = r + b1[t];

    int h = t >> 5, lane = t & 31;
    float elv = f * al1[h * DD + lane];
    float erv = f * ar1[h * DD + lane];
#pragma unroll
    for (int o = 16; o > 0; o >>= 1) {
        elv += __shfl_down_sync(0xffffffffu, elv, o);
        erv += __shfl_down_sync(0xffffffffu, erv, o);
    }
    if (lane == 0) { g_el1[n * HH + h] = elv; g_er1[n * HH + h] = erv; }

    int gid = n * F1 + t;
    if (gid < GG * DD) { g_gsum[gid] = 0.f; g_gmax[gid] = -INFINITY; }
}

// ---------------- CSR build: histogram ------------------------------------
__global__ void __launch_bounds__(256) kHist(const int* __restrict__ dst)
{
    int e = blockIdx.x * 256 + threadIdx.x;
    if (e < EE) atomicAdd(&g_cnt[dst[e]], 1);
}

// ---------------- CSR build: single-block exclusive scan ------------------
__global__ void __launch_bounds__(1024) kScan()
{
    __shared__ int warpsum[32];
    __shared__ int s_run;
    int t = threadIdx.x, lane = t & 31, wid = t >> 5;
    if (t == 0) s_run = 0;
    __syncthreads();
    for (int base = 0; base < NN; base += 1024) {
        int idx = base + t;
        int v = (idx < NN) ? g_cnt[idx] : 0;
        int x = v;
#pragma unroll
        for (int o = 1; o < 32; o <<= 1) {
            int y = __shfl_up_sync(0xffffffffu, x, o);
            if (lane >= o) x += y;
        }
        if (lane == 31) warpsum[wid] = x;
        __syncthreads();
        if (wid == 0) {
            int y = warpsum[lane];
#pragma unroll
            for (int o = 1; o < 32; o <<= 1) {
                int z = __shfl_up_sync(0xffffffffu, y, o);
                if (lane >= o) y += z;
            }
            warpsum[lane] = y;
        }
        __syncthreads();
        int excl = x - v + (wid > 0 ? warpsum[wid - 1] : 0) + s_run;
        if (idx < NN) { g_rowptr[idx] = excl; g_cursor[idx] = excl; }
        __syncthreads();
        if (t == 0) s_run += warpsum[31];
        __syncthreads();
    }
    if (t == 0) g_rowptr[NN] = s_run;
}

// ---------------- CSR build: scatter src by dst ---------------------------
__global__ void __launch_bounds__(256) kScatter(
    const int* __restrict__ src, const int* __restrict__ dst)
{
    int e = blockIdx.x * 256 + threadIdx.x;
    if (e >= EE) return;
    int pos = atomicAdd(&g_cursor[dst[e]], 1);
    g_csrc[pos] = src[e];
}

// ---------------- Fused per-node GAT layer --------------------------------
// layer==0: feats=g_feat1, el/er=1, seed=g_out1, epilogue: h1 = ELU(out)
// layer==1: feats=g_feat2, el/er=2, seed=b2+h1, epilogue: head-mean + readout
__global__ void __launch_bounds__(256) kNode(
    int layer, const float* __restrict__ b2,
    const int* __restrict__ gids, const float* __restrict__ Ww,
    const float* __restrict__ bw)
{
    int n = blockIdx.x;
    int t = threadIdx.x;
    int h = t >> 5;

    const float* feat = layer ? g_feat2 : g_feat1;
    const float* el   = layer ? g_el2   : g_el1;
    const float* er   = layer ? g_er2   : g_er1;

    __shared__ float sh_a[128 * 8];
    __shared__ int   sh_s[128];
    __shared__ float sh_er[8], sh_m[8], sh_inv[8];
    __shared__ float sh_red[64];

    if (t < 8) sh_er[t] = er[n * HH + t];
    int r0  = g_rowptr[n];
    int deg = g_rowptr[n + 1] - r0;
    __syncthreads();

    // pass A: per-head max over incident edges
    if (t < 64) {
        int rep = t >> 3, hh = t & 7;
        float mx = -INFINITY;
        float erh = sh_er[hh];
        for (int j = rep; j < deg; j += 8) {
            int sj = g_csrc[r0 + j];
            float e = el[sj * HH + hh] + erh;
            e = e > 0.f ? e : 0.2f * e;
            mx = fmaxf(mx, e);
        }
        sh_red[t] = mx;
    }
    __syncthreads();
    if (t < 8) {
        float mx = sh_red[t];
#pragma unroll
        for (int rep = 1; rep < 8; rep++) mx = fmaxf(mx, sh_red[rep * 8 + t]);
        sh_m[t] = mx;
    }
    __syncthreads();

    // pass B: per-head exp-sum
    if (t < 64) {
        int rep = t >> 3, hh = t & 7;
        float s = 0.f;
        float erh = sh_er[hh], mh = sh_m[hh];
        for (int j = rep; j < deg; j += 8) {
            int sj = g_csrc[r0 + j];
            float e = el[sj * HH + hh] + erh;
            e = e > 0.f ? e : 0.2f * e;
            s += __expf(e - mh);
        }
        sh_red[t] = s;
    }
    __syncthreads();
    if (t < 8) {
        float s = sh_red[t];
#pragma unroll
        for (int rep = 1; rep < 8; rep++) s += sh_red[rep * 8 + t];
        sh_inv[t] = 1.f / fmaxf(s, 1e-9f);
    }
    __syncthreads();

    // pass C: weighted aggregation into registers (tiled over edges)
    float acc = layer ? (b2[t] + g_h1[(size_t)n * F1 + t])
                      : g_out1[(size_t)n * F1 + t];
    for (int tile = 0; tile < deg; tile += 128) {
        int cnt = min(128, deg - tile);
        for (int i = t; i < cnt * 8; i += 256) {
            int j = i >> 3, hh = i & 7;
            int sj = g_csrc[r0 + tile + j];
            if (hh == 0) sh_s[j] = sj;
            float e = el[sj * HH + hh] + sh_er[hh];
            e = e > 0.f ? e : 0.2f * e;
            sh_a[j * 8 + hh] = __expf(e - sh_m[hh]) * sh_inv[hh];
        }
        __syncthreads();
#pragma unroll 4
        for (int j = 0; j < cnt; j++) {
            acc += sh_a[j * 8 + h] * feat[(size_t)sh_s[j] * F1 + t];
        }
        __syncthreads();
    }

    if (layer == 0) {
        // ELU -> h1
        g_h1[(size_t)n * F1 + t] = acc > 0.f ? acc : expm1f(acc);
    } else {
        // fused head-mean, gate, graph readout
        __shared__ float sh_o[256];
        __shared__ float sh_bw;
        if (t == 0) sh_bw = bw[0];
        sh_o[t] = acc;
        __syncthreads();
        if (t < 32) {
            float s = 0.f;
#pragma unroll
            for (int hh = 0; hh < 8; hh++) s += sh_o[hh * DD + t];
            float h2 = s * 0.125f + 0.0f;          // canonicalize -0
            float wv = h2 * Ww[t];
#pragma unroll
            for (int o = 16; o > 0; o >>= 1)
                wv += __shfl_xor_sync(0xffffffffu, wv, o);
            float w = 1.f / (1.f + __expf(-(wv + sh_bw)));
            int g = gids[n];
            atomicAdd(&g_gsum[g * DD + t], w * h2);
            atomicMaxF(&g_gmax[g * DD + t], h2);
        }
    }
}

// ---------------- Stage F: feat2 = h1 @ W2  (N x 256 x 256) ---------------
__global__ void __launch_bounds__(256) kGemm2(const float* __restrict__ W2)
{
    __shared__ float hs[32][F1];
    int row0 = blockIdx.x * 32;
    int rows = NN - row0; if (rows > 32) rows = 32;

    for (int i = threadIdx.x; i < 32 * 64; i += 256) {
        int r = i >> 6, c4 = i & 63;
        float4 v = (r < rows) ? ((const float4*)(g_h1 + (size_t)(row0 + r) * F1))[c4]
                              : make_float4(0.f, 0.f, 0.f, 0.f);
        ((float4*)&hs[r][0])[c4] = v;
    }
    __syncthreads();

    int cg = threadIdx.x & 63;
    int rg = threadIdx.x >> 6;
    float acc[8][4];
#pragma unroll
    for (int i = 0; i < 8; i++) { acc[i][0] = acc[i][1] = acc[i][2] = acc[i][3] = 0.f; }

    const float4* W2v = (const float4*)W2;
#pragma unroll 4
    for (int k = 0; k < F1; k++) {
        float4 w = W2v[k * 64 + cg];
#pragma unroll
        for (int i = 0; i < 8; i++) {
            float xv = hs[rg * 8 + i][k];
            acc[i][0] += xv * w.x; acc[i][1] += xv * w.y;
            acc[i][2] += xv * w.z; acc[i][3] += xv * w.w;
        }
    }
#pragma unroll
    for (int i = 0; i < 8; i++) {
        int r = rg * 8 + i;
        if (r < rows)
            ((float4*)(g_feat2 + (size_t)(row0 + r) * F1))[cg] =
                make_float4(acc[i][0], acc[i][1], acc[i][2], acc[i][3]);
    }
}

// ---------------- Stage F2: layer-2 attention dots ------------------------
__global__ void __launch_bounds__(256) kPrep2(
    const float* __restrict__ al2, const float* __restrict__ ar2)
{
    int n = blockIdx.x, t = threadIdx.x;
    float f = g_feat2[n * F1 + t];
    int h = t >> 5, lane = t & 31;
    float elv = f * al2[h * DD + lane];
    float erv = f * ar2[h * DD + lane];
#pragma unroll
    for (int o = 16; o > 0; o >>= 1) {
        elv += __shfl_down_sync(0xffffffffu, elv, o);
        erv += __shfl_down_sync(0xffffffffu, erv, o);
    }
    if (lane == 0) { g_el2[n * HH + h] = elv; g_er2[n * HH + h] = erv; }
}

// ---------------- Stage H: MLP predictor ----------------------------------
__global__ void __launch_bounds__(128) kH(
    const float* __restrict__ Wp1, const float* __restrict__ bp1,
    const float* __restrict__ gamma, const float* __restrict__ beta,
    const float* __restrict__ rm, const float* __restrict__ rv,
    const float* __restrict__ Wp2, const float* __restrict__ bp2,
    float* __restrict__ outp)
{
    int g = blockIdx.x, t = threadIdx.x;
    __shared__ float gs[64];
    __shared__ float wsum[4];
    if (t < 32) gs[t] = g_gsum[g * DD + t];
    else if (t < 64) {
        float mv = g_gmax[g * DD + (t - 32)];
        if (!isfinite(mv)) mv = 0.f;
        gs[t] = mv;
    }
    __syncthreads();
    float acc = bp1[t];
#pragma unroll
    for (int k = 0; k < 64; k++) acc += gs[k] * Wp1[k * HIDN + t];
    acc = fmaxf(acc, 0.f);
    acc = (acc - rm[t]) * rsqrtf(rv[t] + 1e-5f) * gamma[t] + beta[t];
    float v = acc * Wp2[t];
#pragma unroll
    for (int o = 16; o > 0; o >>= 1) v += __shfl_xor_sync(0xffffffffu, v, o);
    if ((t & 31) == 0) wsum[t >> 5] = v;
    __syncthreads();
    if (t == 0) outp[g] = wsum[0] + wsum[1] + wsum[2] + wsum[3] + bp2[0];
}

// ---------------- launcher ------------------------------------------------
extern "C" void kernel_launch(void* const* d_in, const int* in_sizes, int n_in,
                              void* d_out, int out_size)
{
    const float* x     = (const float*)d_in[0];
    const int*   src   = (const int*)  d_in[1];
    const int*   dst   = (const int*)  d_in[2];
    const int*   gids  = (const int*)  d_in[3];
    const float* W1    = (const float*)d_in[4];
    const float* al1   = (const float*)d_in[5];
    const float* ar1   = (const float*)d_in[6];
    const float* b1    = (const float*)d_in[7];
    const float* resW1 = (const float*)d_in[8];
    const float* W2    = (const float*)d_in[9];
    const float* al2   = (const float*)d_in[10];
    const float* ar2   = (const float*)d_in[11];
    const float* b2    = (const float*)d_in[12];
    const float* Ww    = (const float*)d_in[13];
    const float* bw    = (const float*)d_in[14];
    const float* Wp1   = (const float*)d_in[15];
    const float* bp1   = (const float*)d_in[16];
    const float* gamma = (const float*)d_in[17];
    const float* beta  = (const float*)d_in[18];
    const float* rm    = (const float*)d_in[19];
    const float* rv    = (const float*)d_in[20];
    const float* Wp2   = (const float*)d_in[21];
    const float* bp2   = (const float*)d_in[22];
    float* outp = (float*)d_out;

    int eb = (EE + 255) / 256;

    kA<<<NN, 256>>>(x, W1, resW1, b1, al1, ar1);   // also zeros g_cnt, gsum/gmax
    kHist<<<eb, 256>>>(dst);
    kScan<<<1, 1024>>>();
    kScatter<<<eb, 256>>>(src, dst);
    kNode<<<NN, 256>>>(0, b2, gids, Ww, bw);       // layer 1 (fused max/exp/agg/ELU)
    kGemm2<<<(NN + 31) / 32, 256>>>(W2);
    kPrep2<<<NN, 256>>>(al2, ar2);
    kNode<<<NN, 256>>>(1, b2, gids, Ww, bw);       // layer 2 (+ head-mean + readout)
    kH<<<GG, 128>>>(Wp1, bp1, gamma, beta, rm, rv, Wp2, bp2, outp);
}

// round 5
// speedup vs baseline: 1.3499x; 1.3229x over previous
#include <cuda_runtime.h>
#include <math.h>

#define NN   50000
#define EE   800000
#define IN_F 30
#define HH   8
#define DD   32
#define GG   512
#define HIDN 128
#define F1   256            // H*D

// ---------------- device scratch (no allocation allowed) ----------------
__device__ float g_feat1[NN * F1];
__device__ float g_out1 [NN * F1];   // layer-1 seed: x@resW1 + b1
__device__ float g_h1   [NN * F1];
__device__ float g_feat2[NN * F1];
__device__ float g_el1[NN * HH], g_er1[NN * HH];
__device__ float g_el2[NN * HH], g_er2[NN * HH];
__device__ float g_gsum[GG * DD], g_gmax[GG * DD];
// CSR-by-dst
__device__ int g_cnt[NN];
__device__ int g_rowptr[NN + 1];
__device__ int g_cursor[NN];
__device__ int g_csrc[EE];

__device__ __forceinline__ void atomicMaxF(float* addr, float v) {
    if (v >= 0.0f) atomicMax((int*)addr, __float_as_int(v));
    else           atomicMin((unsigned int*)addr, __float_as_uint(v));
}

// ---------------- Stage A: layer-1 projection + attention dots + inits ----
__global__ void __launch_bounds__(256) kA(
    const float* __restrict__ x, const float* __restrict__ W1,
    const float* __restrict__ resW1, const float* __restrict__ b1,
    const float* __restrict__ al1, const float* __restrict__ ar1)
{
    int n = blockIdx.x;
    int t = threadIdx.x;
    __shared__ float xs[IN_F];
    if (t < IN_F) xs[t] = x[n * IN_F + t];
    if (t == 0) g_cnt[n] = 0;
    __syncthreads();

    float f = 0.f, r = 0.f;
#pragma unroll
    for (int k = 0; k < IN_F; k++) {
        float xv = xs[k];
        f += xv * W1[k * F1 + t];
        r += xv * resW1[k * F1 + t];
    }
    g_feat1[n * F1 + t] = f;
    g_out1[n * F1 + t]  = r + b1[t];

    int h = t >> 5, lane = t & 31;
    float elv = f * al1[h * DD + lane];
    float erv = f * ar1[h * DD + lane];
#pragma unroll
    for (int o = 16; o > 0; o >>= 1) {
        elv += __shfl_down_sync(0xffffffffu, elv, o);
        erv += __shfl_down_sync(0xffffffffu, erv, o);
    }
    if (lane == 0) { g_el1[n * HH + h] = elv; g_er1[n * HH + h] = erv; }

    int gid = n * F1 + t;
    if (gid < GG * DD) { g_gsum[gid] = 0.f; g_gmax[gid] = -INFINITY; }
}

// ---------------- CSR build: histogram ------------------------------------
__global__ void __launch_bounds__(256) kHist(const int* __restrict__ dst)
{
    int e = blockIdx.x * 256 + threadIdx.x;
    if (e < EE) atomicAdd(&g_cnt[dst[e]], 1);
}

// ---------------- CSR build: single-block exclusive scan ------------------
__global__ void __launch_bounds__(1024) kScan()
{
    __shared__ int warpsum[32];
    __shared__ int s_run;
    int t = threadIdx.x, lane = t & 31, wid = t >> 5;
    if (t == 0) s_run = 0;
    __syncthreads();
    for (int base = 0; base < NN; base += 1024) {
        int idx = base + t;
        int v = (idx < NN) ? g_cnt[idx] : 0;
        int x = v;
#pragma unroll
        for (int o = 1; o < 32; o <<= 1) {
            int y = __shfl_up_sync(0xffffffffu, x, o);
            if (lane >= o) x += y;
        }
        if (lane == 31) warpsum[wid] = x;
        __syncthreads();
        if (wid == 0) {
            int y = warpsum[lane];
#pragma unroll
            for (int o = 1; o < 32; o <<= 1) {
                int z = __shfl_up_sync(0xffffffffu, y, o);
                if (lane >= o) y += z;
            }
            warpsum[lane] = y;
        }
        __syncthreads();
        int excl = x - v + (wid > 0 ? warpsum[wid - 1] : 0) + s_run;
        if (idx < NN) { g_rowptr[idx] = excl; g_cursor[idx] = excl; }
        __syncthreads();
        if (t == 0) s_run += warpsum[31];
        __syncthreads();
    }
    if (t == 0) g_rowptr[NN] = s_run;
}

// ---------------- CSR build: scatter src by dst ---------------------------
__global__ void __launch_bounds__(256) kScatter(
    const int* __restrict__ src, const int* __restrict__ dst)
{
    int e = blockIdx.x * 256 + threadIdx.x;
    if (e >= EE) return;
    int pos = atomicAdd(&g_cursor[dst[e]], 1);
    g_csrc[pos] = src[e];
}

// ---------------- Fused single-pass GAT layer (max-free softmax) ----------
// out = seed + (sum_j exp(leaky(e_j)) * feat[src_j]) / max(sum_j exp, 1e-9)
__global__ void __launch_bounds__(256) kNode(
    int layer, const float* __restrict__ b2,
    const int* __restrict__ gids, const float* __restrict__ Ww,
    const float* __restrict__ bw)
{
    int n = blockIdx.x;
    int t = threadIdx.x;

    const float* feat = layer ? g_feat2 : g_feat1;
    const float* el   = layer ? g_el2   : g_el1;
    const float* er   = layer ? g_er2   : g_er1;

    __shared__ float sh_er[8];
    __shared__ float sh_w[32 * 8];
    __shared__ int   sh_s32[32];
    __shared__ float sh_sf[8];
    __shared__ float sh_acc[3 * 256];
    __shared__ float sh_o[256];
    __shared__ float sh_bw;

    int r0  = g_rowptr[n];
    int deg = g_rowptr[n + 1] - r0;
    if (t < 8) sh_er[t] = er[n * HH + t];
    if (t == 0 && layer) sh_bw = bw[0];

    int g  = t >> 6;        // edge subgroup 0-3
    int c  = t & 63;        // float4 column (features 4c..4c+3)
    int hc = c >> 3;        // head of this feature group
    int j  = t >> 3;        // edge slot for w-compute
    int hh = t & 7;         // head for w-compute

    float4 acc = make_float4(0.f, 0.f, 0.f, 0.f);
    float s_part = 0.f;
    __syncthreads();

    for (int tile = 0; tile < deg; tile += 32) {
        int cnt = min(32, deg - tile);
        if (j < cnt) {
            int sj = g_csrc[r0 + tile + j];
            if (hh == 0) sh_s32[j] = sj;
            float e = el[sj * HH + hh] + sh_er[hh];
            e = e > 0.f ? e : 0.2f * e;
            sh_w[t] = __expf(e);          // t == j*8+hh
        }
        __syncthreads();
#pragma unroll 4
        for (int j2 = g; j2 < cnt; j2 += 4) {
            float w = sh_w[j2 * 8 + hc];
            float4 fv = ((const float4*)(feat + (size_t)sh_s32[j2] * F1))[c];
            acc.x += w * fv.x; acc.y += w * fv.y;
            acc.z += w * fv.z; acc.w += w * fv.w;
        }
        if (t < 8) {
            float s = 0.f;
            for (int j2 = 0; j2 < cnt; j2++) s += sh_w[j2 * 8 + t];
            s_part += s;
        }
        __syncthreads();
    }

    if (t < 8) sh_sf[t] = s_part;
    if (g > 0) *(float4*)&sh_acc[(g - 1) * 256 + c * 4] = acc;
    __syncthreads();

    if (layer == 0) {
        if (g == 0) {
            float4 a1 = *(float4*)&sh_acc[c * 4];
            float4 a2 = *(float4*)&sh_acc[256 + c * 4];
            float4 a3 = *(float4*)&sh_acc[512 + c * 4];
            float inv = 1.f / fmaxf(sh_sf[hc], 1e-9f);
            float4 seed = *(const float4*)(g_out1 + (size_t)n * F1 + c * 4);
            float4 o;
            o.x = seed.x + (acc.x + a1.x + a2.x + a3.x) * inv;
            o.y = seed.y + (acc.y + a1.y + a2.y + a3.y) * inv;
            o.z = seed.z + (acc.z + a1.z + a2.z + a3.z) * inv;
            o.w = seed.w + (acc.w + a1.w + a2.w + a3.w) * inv;
            o.x = o.x > 0.f ? o.x : expm1f(o.x);
            o.y = o.y > 0.f ? o.y : expm1f(o.y);
            o.z = o.z > 0.f ? o.z : expm1f(o.z);
            o.w = o.w > 0.f ? o.w : expm1f(o.w);
            *(float4*)(g_h1 + (size_t)n * F1 + c * 4) = o;
        }
    } else {
        if (g == 0) {
            float4 a1 = *(float4*)&sh_acc[c * 4];
            float4 a2 = *(float4*)&sh_acc[256 + c * 4];
            float4 a3 = *(float4*)&sh_acc[512 + c * 4];
            float inv = 1.f / fmaxf(sh_sf[hc], 1e-9f);
            float4 seed;
            const float4 bb = *(const float4*)(b2 + c * 4);
            const float4 hv = *(const float4*)(g_h1 + (size_t)n * F1 + c * 4);
            seed.x = bb.x + hv.x; seed.y = bb.y + hv.y;
            seed.z = bb.z + hv.z; seed.w = bb.w + hv.w;
            float4 o;
            o.x = seed.x + (acc.x + a1.x + a2.x + a3.x) * inv;
            o.y = seed.y + (acc.y + a1.y + a2.y + a3.y) * inv;
            o.z = seed.z + (acc.z + a1.z + a2.z + a3.z) * inv;
            o.w = seed.w + (acc.w + a1.w + a2.w + a3.w) * inv;
            *(float4*)&sh_o[c * 4] = o;
        }
        __syncthreads();
        if (t < 32) {
            float s = 0.f;
#pragma unroll
            for (int h2i = 0; h2i < 8; h2i++) s += sh_o[h2i * DD + t];
            float h2 = s * 0.125f + 0.0f;          // canonicalize -0
            float wv = h2 * Ww[t];
#pragma unroll
            for (int o = 16; o > 0; o >>= 1)
                wv += __shfl_xor_sync(0xffffffffu, wv, o);
            float w = 1.f / (1.f + __expf(-(wv + sh_bw)));
            int gg = gids[n];
            atomicAdd(&g_gsum[gg * DD + t], w * h2);
            atomicMaxF(&g_gmax[gg * DD + t], h2);
        }
    }
}

// ---------------- Stage F: feat2 = h1 @ W2  (64 rows x 256 cols / block) --
#define GR 64
__global__ void __launch_bounds__(256) kGemm2(const float* __restrict__ W2)
{
    __shared__ float hsT[256 * GR];   // k-major: hsT[k*64 + r], 64 KB
    int row0 = blockIdx.x * GR;
    int t = threadIdx.x;
    int rows = NN - row0; if (rows > GR) rows = GR;

    // load + transpose h1 tile
    {
        int r  = t & 63;
        int kc = t >> 6;              // k-chunk of 64
        const float4* srcp = (const float4*)(g_h1 + (size_t)(row0 + r) * F1);
        bool valid = r < rows;
#pragma unroll
        for (int q = 0; q < 16; q++) {
            int k0 = kc * 64 + q * 4;
            float4 v = valid ? srcp[k0 >> 2] : make_float4(0.f, 0.f, 0.f, 0.f);
            hsT[(k0 + 0) * GR + r] = v.x;
            hsT[(k0 + 1) * GR + r] = v.y;
            hsT[(k0 + 2) * GR + r] = v.z;
            hsT[(k0 + 3) * GR + r] = v.w;
        }
    }
    __syncthreads();

    int cg = t & 31;   // 8-col group
    int rg = t >> 5;   // 8-row group
    float acc[8][8];
#pragma unroll
    for (int i = 0; i < 8; i++)
#pragma unroll
        for (int jj = 0; jj < 8; jj++) acc[i][jj] = 0.f;

    const float4* W2v = (const float4*)W2;
#pragma unroll 2
    for (int k = 0; k < 256; k++) {
        float4 w0 = W2v[k * 64 + cg * 2];
        float4 w1 = W2v[k * 64 + cg * 2 + 1];
        float4 a0 = *(const float4*)&hsT[k * GR + rg * 8];
        float4 a1 = *(const float4*)&hsT[k * GR + rg * 8 + 4];
        float ar[8] = {a0.x, a0.y, a0.z, a0.w, a1.x, a1.y, a1.z, a1.w};
        float wr[8] = {w0.x, w0.y, w0.z, w0.w, w1.x, w1.y, w1.z, w1.w};
#pragma unroll
        for (int i = 0; i < 8; i++)
#pragma unroll
            for (int jj = 0; jj < 8; jj++)
                acc[i][jj] += ar[i] * wr[jj];
    }

#pragma unroll
    for (int i = 0; i < 8; i++) {
        int rr = rg * 8 + i;
        if (rr < rows) {
            float* dstp = g_feat2 + (size_t)(row0 + rr) * F1 + cg * 8;
            *(float4*)dstp       = make_float4(acc[i][0], acc[i][1], acc[i][2], acc[i][3]);
            *(float4*)(dstp + 4) = make_float4(acc[i][4], acc[i][5], acc[i][6], acc[i][7]);
        }
    }
}

// ---------------- Stage F2: layer-2 attention dots ------------------------
__global__ void __launch_bounds__(256) kPrep2(
    const float* __restrict__ al2, const float* __restrict__ ar2)
{
    int n = blockIdx.x, t = threadIdx.x;
    float f = g_feat2[n * F1 + t];
    int h = t >> 5, lane = t & 31;
    float elv = f * al2[h * DD + lane];
    float erv = f * ar2[h * DD + lane];
#pragma unroll
    for (int o = 16; o > 0; o >>= 1) {
        elv += __shfl_down_sync(0xffffffffu, elv, o);
        erv += __shfl_down_sync(0xffffffffu, erv, o);
    }
    if (lane == 0) { g_el2[n * HH + h] = elv; g_er2[n * HH + h] = erv; }
}

// ---------------- Stage H: MLP predictor ----------------------------------
__global__ void __launch_bounds__(128) kH(
    const float* __restrict__ Wp1, const float* __restrict__ bp1,
    const float* __restrict__ gamma, const float* __restrict__ beta,
    const float* __restrict__ rm, const float* __restrict__ rv,
    const float* __restrict__ Wp2, const float* __restrict__ bp2,
    float* __restrict__ outp)
{
    int g = blockIdx.x, t = threadIdx.x;
    __shared__ float gs[64];
    __shared__ float wsum[4];
    if (t < 32) gs[t] = g_gsum[g * DD + t];
    else if (t < 64) {
        float mv = g_gmax[g * DD + (t - 32)];
        if (!isfinite(mv)) mv = 0.f;
        gs[t] = mv;
    }
    __syncthreads();
    float acc = bp1[t];
#pragma unroll
    for (int k = 0; k < 64; k++) acc += gs[k] * Wp1[k * HIDN + t];
    acc = fmaxf(acc, 0.f);
    acc = (acc - rm[t]) * rsqrtf(rv[t] + 1e-5f) * gamma[t] + beta[t];
    float v = acc * Wp2[t];
#pragma unroll
    for (int o = 16; o > 0; o >>= 1) v += __shfl_xor_sync(0xffffffffu, v, o);
    if ((t & 31) == 0) wsum[t >> 5] = v;
    __syncthreads();
    if (t == 0) outp[g] = wsum[0] + wsum[1] + wsum[2] + wsum[3] + bp2[0];
}

// ---------------- launcher ------------------------------------------------
extern "C" void kernel_launch(void* const* d_in, const int* in_sizes, int n_in,
                              void* d_out, int out_size)
{
    const float* x     = (const float*)d_in[0];
    const int*   src   = (const int*)  d_in[1];
    const int*   dst   = (const int*)  d_in[2];
    const int*   gids  = (const int*)  d_in[3];
    const float* W1    = (const float*)d_in[4];
    const float* al1   = (const float*)d_in[5];
    const float* ar1   = (const float*)d_in[6];
    const float* b1    = (const float*)d_in[7];
    const float* resW1 = (const float*)d_in[8];
    const float* W2    = (const float*)d_in[9];
    const float* al2   = (const float*)d_in[10];
    const float* ar2   = (const float*)d_in[11];
    const float* b2    = (const float*)d_in[12];
    const float* Ww    = (const float*)d_in[13];
    const float* bw    = (const float*)d_in[14];
    const float* Wp1   = (const float*)d_in[15];
    const float* bp1   = (const float*)d_in[16];
    const float* gamma = (const float*)d_in[17];
    const float* beta  = (const float*)d_in[18];
    const float* rm    = (const float*)d_in[19];
    const float* rv    = (const float*)d_in[20];
    const float* Wp2   = (const float*)d_in[21];
    const float* bp2   = (const float*)d_in[22];
    float* outp = (float*)d_out;

    int eb = (EE + 255) / 256;

    kA<<<NN, 256>>>(x, W1, resW1, b1, al1, ar1);
    kHist<<<eb, 256>>>(dst);
    kScan<<<1, 1024>>>();
    kScatter<<<eb, 256>>>(src, dst);
    kNode<<<NN, 256>>>(0, b2, gids, Ww, bw);
    kGemm2<<<(NN + GR - 1) / GR, 256>>>(W2);
    kPrep2<<<NN, 256>>>(al2, ar2);
    kNode<<<NN, 256>>>(1, b2, gids, Ww, bw);
    kH<<<GG, 128>>>(Wp1, bp1, gamma, beta, rm, rv, Wp2, bp2, outp);
}

// round 9
// speedup vs baseline: 1.7283x; 1.2803x over previous
#include <cuda_runtime.h>
#include <math.h>
#include <stdint.h>

#define NN   50000
#define EE   800000
#define IN_F 30
#define HH   8
#define DD   32
#define GG   512
#define HIDN 128
#define F1   256            // H*D

// ---------------- device scratch (no allocation allowed) ----------------
__device__ float g_feat1[NN * F1];
__device__ float g_out1 [NN * F1];   // layer-1 seed: x@resW1 + b1
__device__ float g_h1   [NN * F1];
__device__ float g_feat2[NN * F1];
__device__ float g_el1[NN * HH], g_er1[NN * HH];
__device__ float g_el2[NN * HH], g_er2[NN * HH];
__device__ float g_gsum[GG * DD], g_gmax[GG * DD];
// CSR-by-dst
__device__ int g_cnt[NN];
__device__ int g_rowptr[NN + 1];
__device__ int g_cursor[NN];
__device__ int g_csrc[EE];

__device__ __forceinline__ void atomicMaxF(float* addr, float v) {
    if (v >= 0.0f) atomicMax((int*)addr, __float_as_int(v));
    else           atomicMin((unsigned int*)addr, __float_as_uint(v));
}

__device__ __forceinline__ uint32_t f2tf32(float f) {
    uint32_t r;
    asm("cvt.rna.tf32.f32 %0, %1;" : "=r"(r) : "f"(f));
    return r;
}

__device__ __forceinline__ void mma_tf32(float* c, const uint32_t* a, const uint32_t* b) {
    asm volatile(
        "mma.sync.aligned.m16n8k8.row.col.f32.tf32.tf32.f32 "
        "{%0,%1,%2,%3}, {%4,%5,%6,%7}, {%8,%9}, {%0,%1,%2,%3};"
        : "+f"(c[0]), "+f"(c[1]), "+f"(c[2]), "+f"(c[3])
        : "r"(a[0]), "r"(a[1]), "r"(a[2]), "r"(a[3]), "r"(b[0]), "r"(b[1]));
}

// ---------------- Stage A: layer-1 projection + attention dots + inits ----
__global__ void __launch_bounds__(256) kA(
    const float* __restrict__ x, const float* __restrict__ W1,
    const float* __restrict__ resW1, const float* __restrict__ b1,
    const float* __restrict__ al1, const float* __restrict__ ar1)
{
    int n = blockIdx.x;
    int t = threadIdx.x;
    __shared__ float xs[IN_F];
    if (t < IN_F) xs[t] = x[n * IN_F + t];
    if (t == 0) g_cnt[n] = 0;
    __syncthreads();

    float f = 0.f, r = 0.f;
#pragma unroll
    for (int k = 0; k < IN_F; k++) {
        float xv = xs[k];
        f += xv * W1[k * F1 + t];
        r += xv * resW1[k * F1 + t];
    }
    g_feat1[n * F1 + t] = f;
    g_out1[n * F1 + t]  = r + b1[t];

    int h = t >> 5, lane = t & 31;
    float elv = f * al1[h * DD + lane];
    float erv = f * ar1[h * DD + lane];
#pragma unroll
    for (int o = 16; o > 0; o >>= 1) {
        elv += __shfl_down_sync(0xffffffffu, elv, o);
        erv += __shfl_down_sync(0xffffffffu, erv, o);
    }
    if (lane == 0) { g_el1[n * HH + h] = elv; g_er1[n * HH + h] = erv; }

    int gid = n * F1 + t;
    if (gid < GG * DD) { g_gsum[gid] = 0.f; g_gmax[gid] = -INFINITY; }
}

// ---------------- CSR build: histogram ------------------------------------
__global__ void __launch_bounds__(256) kHist(const int* __restrict__ dst)
{
    int e = blockIdx.x * 256 + threadIdx.x;
    if (e < EE) atomicAdd(&g_cnt[dst[e]], 1);
}

// ---------------- CSR build: single-block exclusive scan ------------------
__global__ void __launch_bounds__(1024) kScan()
{
    __shared__ int warpsum[32];
    __shared__ int s_run;
    int t = threadIdx.x, lane = t & 31, wid = t >> 5;
    if (t == 0) s_run = 0;
    __syncthreads();
    for (int base = 0; base < NN; base += 1024) {
        int idx = base + t;
        int v = (idx < NN) ? g_cnt[idx] : 0;
        int x = v;
#pragma unroll
        for (int o = 1; o < 32; o <<= 1) {
            int y = __shfl_up_sync(0xffffffffu, x, o);
            if (lane >= o) x += y;
        }
        if (lane == 31) warpsum[wid] = x;
        __syncthreads();
        if (wid == 0) {
            int y = warpsum[lane];
#pragma unroll
            for (int o = 1; o < 32; o <<= 1) {
                int z = __shfl_up_sync(0xffffffffu, y, o);
                if (lane >= o) y += z;
            }
            warpsum[lane] = y;
        }
        __syncthreads();
        int excl = x - v + (wid > 0 ? warpsum[wid - 1] : 0) + s_run;
        if (idx < NN) { g_rowptr[idx] = excl; g_cursor[idx] = excl; }
        __syncthreads();
        if (t == 0) s_run += warpsum[31];
        __syncthreads();
    }
    if (t == 0) g_rowptr[NN] = s_run;
}

// ---------------- CSR build: scatter src by dst ---------------------------
__global__ void __launch_bounds__(256) kScatter(
    const int* __restrict__ src, const int* __restrict__ dst)
{
    int e = blockIdx.x * 256 + threadIdx.x;
    if (e >= EE) return;
    int pos = atomicAdd(&g_cursor[dst[e]], 1);
    g_csrc[pos] = src[e];
}

// ---------------- Fused single-pass GAT layer (max-free softmax) ----------
__global__ void __launch_bounds__(256) kNode(
    int layer, const float* __restrict__ b2,
    const int* __restrict__ gids, const float* __restrict__ Ww,
    const float* __restrict__ bw)
{
    int n = blockIdx.x;
    int t = threadIdx.x;

    const float* feat = layer ? g_feat2 : g_feat1;
    const float* el   = layer ? g_el2   : g_el1;
    const float* er   = layer ? g_er2   : g_er1;

    __shared__ float sh_er[8];
    __shared__ float sh_w[32 * 8];
    __shared__ int   sh_s32[32];
    __shared__ float sh_sf[8];
    __shared__ float sh_acc[3 * 256];
    __shared__ float sh_o[256];
    __shared__ float sh_bw;

    int r0  = g_rowptr[n];
    int deg = g_rowptr[n + 1] - r0;
    if (t < 8) sh_er[t] = er[n * HH + t];
    if (t == 0 && layer) sh_bw = bw[0];

    int g  = t >> 6;
    int c  = t & 63;
    int hc = c >> 3;
    int j  = t >> 3;
    int hh = t & 7;

    float4 acc = make_float4(0.f, 0.f, 0.f, 0.f);
    float s_part = 0.f;
    __syncthreads();

    for (int tile = 0; tile < deg; tile += 32) {
        int cnt = min(32, deg - tile);
        if (j < cnt) {
            int sj = g_csrc[r0 + tile + j];
            if (hh == 0) sh_s32[j] = sj;
            float e = el[sj * HH + hh] + sh_er[hh];
            e = e > 0.f ? e : 0.2f * e;
            sh_w[t] = __expf(e);
        }
        __syncthreads();
#pragma unroll 4
        for (int j2 = g; j2 < cnt; j2 += 4) {
            float w = sh_w[j2 * 8 + hc];
            float4 fv = ((const float4*)(feat + (size_t)sh_s32[j2] * F1))[c];
            acc.x += w * fv.x; acc.y += w * fv.y;
            acc.z += w * fv.z; acc.w += w * fv.w;
        }
        if (t < 8) {
            float s = 0.f;
            for (int j2 = 0; j2 < cnt; j2++) s += sh_w[j2 * 8 + t];
            s_part += s;
        }
        __syncthreads();
    }

    if (t < 8) sh_sf[t] = s_part;
    if (g > 0) *(float4*)&sh_acc[(g - 1) * 256 + c * 4] = acc;
    __syncthreads();

    if (layer == 0) {
        if (g == 0) {
            float4 a1 = *(float4*)&sh_acc[c * 4];
            float4 a2 = *(float4*)&sh_acc[256 + c * 4];
            float4 a3 = *(float4*)&sh_acc[512 + c * 4];
            float inv = 1.f / fmaxf(sh_sf[hc], 1e-9f);
            float4 seed = *(const float4*)(g_out1 + (size_t)n * F1 + c * 4);
            float4 o;
            o.x = seed.x + (acc.x + a1.x + a2.x + a3.x) * inv;
            o.y = seed.y + (acc.y + a1.y + a2.y + a3.y) * inv;
            o.z = seed.z + (acc.z + a1.z + a2.z + a3.z) * inv;
            o.w = seed.w + (acc.w + a1.w + a2.w + a3.w) * inv;
            o.x = o.x > 0.f ? o.x : expm1f(o.x);
            o.y = o.y > 0.f ? o.y : expm1f(o.y);
            o.z = o.z > 0.f ? o.z : expm1f(o.z);
            o.w = o.w > 0.f ? o.w : expm1f(o.w);
            *(float4*)(g_h1 + (size_t)n * F1 + c * 4) = o;
        }
    } else {
        if (g == 0) {
            float4 a1 = *(float4*)&sh_acc[c * 4];
            float4 a2 = *(float4*)&sh_acc[256 + c * 4];
            float4 a3 = *(float4*)&sh_acc[512 + c * 4];
            float inv = 1.f / fmaxf(sh_sf[hc], 1e-9f);
            float4 seed;
            const float4 bb = *(const float4*)(b2 + c * 4);
            const float4 hv = *(const float4*)(g_h1 + (size_t)n * F1 + c * 4);
            seed.x = bb.x + hv.x; seed.y = bb.y + hv.y;
            seed.z = bb.z + hv.z; seed.w = bb.w + hv.w;
            float4 o;
            o.x = seed.x + (acc.x + a1.x + a2.x + a3.x) * inv;
            o.y = seed.y + (acc.y + a1.y + a2.y + a3.y) * inv;
            o.z = seed.z + (acc.z + a1.z + a2.z + a3.z) * inv;
            o.w = seed.w + (acc.w + a1.w + a2.w + a3.w) * inv;
            *(float4*)&sh_o[c * 4] = o;
        }
        __syncthreads();
        if (t < 32) {
            float s = 0.f;
#pragma unroll
            for (int h2i = 0; h2i < 8; h2i++) s += sh_o[h2i * DD + t];
            float h2 = s * 0.125f + 0.0f;
            float wv = h2 * Ww[t];
#pragma unroll
            for (int o = 16; o > 0; o >>= 1)
                wv += __shfl_xor_sync(0xffffffffu, wv, o);
            float w = 1.f / (1.f + __expf(-(wv + sh_bw)));
            int gg = gids[n];
            atomicAdd(&g_gsum[gg * DD + t], w * h2);
            atomicMaxF(&g_gmax[gg * DD + t], h2);
        }
    }
}

// ---------------- tf32 mma.sync GEMM: feat2 = h1 @ W2, fused el2/er2 ------
// Block: 128 rows x 128 cols (grid.y selects col half). K=256 in 8 slabs.
#define AS_STRIDE 36
#define BS_STRIDE 136
__global__ void __launch_bounds__(256) kGemmMMA(
    const float* __restrict__ W2,
    const float* __restrict__ al2, const float* __restrict__ ar2)
{
    __shared__ uint32_t as_[128 * AS_STRIDE];
    __shared__ uint32_t bs_[32 * BS_STRIDE];
    __shared__ float sal[128], sar[128];

    int t = threadIdx.x;
    int lane = t & 31, warp = t >> 5;
    int gid = lane >> 2, tid4 = lane & 3;
    int wm = warp >> 1, wn = warp & 1;

    int row0 = blockIdx.x * 128;
    int c0   = blockIdx.y * 128;

    if (t < 128) { sal[t] = al2[c0 + t]; sar[t] = ar2[c0 + t]; }

    float acc[2][8][4];
#pragma unroll
    for (int i = 0; i < 2; i++)
#pragma unroll
        for (int j = 0; j < 8; j++)
#pragma unroll
            for (int q = 0; q < 4; q++) acc[i][j][q] = 0.f;

    for (int s = 0; s < 8; s++) {
        // A slab: 128 rows x 32 k (from h1 col s*32), cvt to tf32
#pragma unroll
        for (int q = 0; q < 4; q++) {
            int p = t + q * 256;          // 1024 float4
            int r = p >> 3, c4 = p & 7;
            float4 v = (row0 + r < NN)
                ? *(const float4*)(g_h1 + (size_t)(row0 + r) * F1 + s * 32 + c4 * 4)
                : make_float4(0.f, 0.f, 0.f, 0.f);
            uint32_t* dstp = &as_[r * AS_STRIDE + c4 * 4];
            dstp[0] = f2tf32(v.x); dstp[1] = f2tf32(v.y);
            dstp[2] = f2tf32(v.z); dstp[3] = f2tf32(v.w);
        }
        // B slab: 32 k x 128 n (W2 rows s*32.., cols c0..), cvt to tf32
#pragma unroll
        for (int q = 0; q < 4; q++) {
            int p = t + q * 256;          // 1024 float4
            int r = p >> 5, c4 = p & 31;
            float4 v = *(const float4*)(W2 + (size_t)(s * 32 + r) * F1 + c0 + c4 * 4);
            uint32_t* dstp = &bs_[r * BS_STRIDE + c4 * 4];
            dstp[0] = f2tf32(v.x); dstp[1] = f2tf32(v.y);
            dstp[2] = f2tf32(v.z); dstp[3] = f2tf32(v.w);
        }
        __syncthreads();

#pragma unroll
        for (int kk = 0; kk < 4; kk++) {
            uint32_t bf[8][2];
            int kb = kk * 8 + tid4;
#pragma unroll
            for (int j = 0; j < 8; j++) {
                int nn = wn * 64 + j * 8 + gid;
                bf[j][0] = bs_[kb * BS_STRIDE + nn];
                bf[j][1] = bs_[(kb + 4) * BS_STRIDE + nn];
            }
#pragma unroll
            for (int i = 0; i < 2; i++) {
                uint32_t af[4];
                int m = wm * 32 + i * 16 + gid;
                af[0] = as_[m * AS_STRIDE + kk * 8 + tid4];
                af[1] = as_[(m + 8) * AS_STRIDE + kk * 8 + tid4];
                af[2] = as_[m * AS_STRIDE + kk * 8 + tid4 + 4];
                af[3] = as_[(m + 8) * AS_STRIDE + kk * 8 + tid4 + 4];
#pragma unroll
                for (int j = 0; j < 8; j++) mma_tf32(acc[i][j], af, bf[j]);
            }
        }
        __syncthreads();
    }

    // epilogue: store feat2 + fused el2/er2 (head = global col / 32)
#pragma unroll
    for (int i = 0; i < 2; i++) {
        int mrow = row0 + wm * 32 + i * 16 + gid;   // rows mrow, mrow+8
        float elv[2][2] = {{0.f, 0.f}, {0.f, 0.f}};
        float erv[2][2] = {{0.f, 0.f}, {0.f, 0.f}};
#pragma unroll
        for (int j = 0; j < 8; j++) {
            int nl = wn * 64 + j * 8 + tid4 * 2;    // col within block
            int hl = j >> 2;                        // local head (0/1)
            float* cc = acc[i][j];
            float w0l = sal[nl], w1l = sal[nl + 1];
            float w0r = sar[nl], w1r = sar[nl + 1];
            if (mrow < NN)
                *(float2*)(g_feat2 + (size_t)mrow * F1 + c0 + nl) =
                    make_float2(cc[0], cc[1]);
            if (mrow + 8 < NN)
                *(float2*)(g_feat2 + (size_t)(mrow + 8) * F1 + c0 + nl) =
                    make_float2(cc[2], cc[3]);
            elv[0][hl] += cc[0] * w0l + cc[1] * w1l;
            elv[1][hl] += cc[2] * w0l + cc[3] * w1l;
            erv[0][hl] += cc[0] * w0r + cc[1] * w1r;
            erv[1][hl] += cc[2] * w0r + cc[3] * w1r;
        }
        // reduce across the 4 quad lanes (tid4)
#pragma unroll
        for (int off = 1; off < 4; off <<= 1) {
#pragma unroll
            for (int rh = 0; rh < 2; rh++)
#pragma unroll
                for (int hl = 0; hl < 2; hl++) {
                    elv[rh][hl] += __shfl_xor_sync(0xffffffffu, elv[rh][hl], off);
                    erv[rh][hl] += __shfl_xor_sync(0xffffffffu, erv[rh][hl], off);
                }
        }
        if (tid4 == 0) {
            int hbase = (c0 >> 5) + wn * 2;
            if (mrow < NN) {
                g_el2[mrow * HH + hbase]     = elv[0][0];
                g_el2[mrow * HH + hbase + 1] = elv[0][1];
                g_er2[mrow * HH + hbase]     = erv[0][0];
                g_er2[mrow * HH + hbase + 1] = erv[0][1];
            }
            if (mrow + 8 < NN) {
                g_el2[(mrow + 8) * HH + hbase]     = elv[1][0];
                g_el2[(mrow + 8) * HH + hbase + 1] = elv[1][1];
                g_er2[(mrow + 8) * HH + hbase]     = erv[1][0];
                g_er2[(mrow + 8) * HH + hbase + 1] = erv[1][1];
            }
        }
    }
}

// ---------------- Stage H: MLP predictor ----------------------------------
__global__ void __launch_bounds__(128) kH(
    const float* __restrict__ Wp1, const float* __restrict__ bp1,
    const float* __restrict__ gamma, const float* __restrict__ beta,
    const float* __restrict__ rm, const float* __restrict__ rv,
    const float* __restrict__ Wp2, const float* __restrict__ bp2,
    float* __restrict__ outp)
{
    int g = blockIdx.x, t = threadIdx.x;
    __shared__ float gs[64];
    __shared__ float wsum[4];
    if (t < 32) gs[t] = g_gsum[g * DD + t];
    else if (t < 64) {
        float mv = g_gmax[g * DD + (t - 32)];
        if (!isfinite(mv)) mv = 0.f;
        gs[t] = mv;
    }
    __syncthreads();
    float acc = bp1[t];
#pragma unroll
    for (int k = 0; k < 64; k++) acc += gs[k] * Wp1[k * HIDN + t];
    acc = fmaxf(acc, 0.f);
    acc = (acc - rm[t]) * rsqrtf(rv[t] + 1e-5f) * gamma[t] + beta[t];
    float v = acc * Wp2[t];
#pragma unroll
    for (int o = 16; o > 0; o >>= 1) v += __shfl_xor_sync(0xffffffffu, v, o);
    if ((t & 31) == 0) wsum[t >> 5] = v;
    __syncthreads();
    if (t == 0) outp[g] = wsum[0] + wsum[1] + wsum[2] + wsum[3] + bp2[0];
}

// ---------------- launcher ------------------------------------------------
extern "C" void kernel_launch(void* const* d_in, const int* in_sizes, int n_in,
                              void* d_out, int out_size)
{
    const float* x     = (const float*)d_in[0];
    const int*   src   = (const int*)  d_in[1];
    const int*   dst   = (const int*)  d_in[2];
    const int*   gids  = (const int*)  d_in[3];
    const float* W1    = (const float*)d_in[4];
    const float* al1   = (const float*)d_in[5];
    const float* ar1   = (const float*)d_in[6];
    const float* b1    = (const float*)d_in[7];
    const float* resW1 = (const float*)d_in[8];
    const float* W2    = (const float*)d_in[9];
    const float* al2   = (const float*)d_in[10];
    const float* ar2   = (const float*)d_in[11];
    const float* b2    = (const float*)d_in[12];
    const float* Ww    = (const float*)d_in[13];
    const float* bw    = (const float*)d_in[14];
    const float* Wp1   = (const float*)d_in[15];
    const float* bp1   = (const float*)d_in[16];
    const float* gamma = (const float*)d_in[17];
    const float* beta  = (const float*)d_in[18];
    const float* rm    = (const float*)d_in[19];
    const float* rv    = (const float*)d_in[20];
    const float* Wp2   = (const float*)d_in[21];
    const float* bp2   = (const float*)d_in[22];
    float* outp = (float*)d_out;

    int eb = (EE + 255) / 256;

    kA<<<NN, 256>>>(x, W1, resW1, b1, al1, ar1);
    kHist<<<eb, 256>>>(dst);
    kScan<<<1, 1024>>>();
    kScatter<<<eb, 256>>>(src, dst);
    kNode<<<NN, 256>>>(0, b2, gids, Ww, bw);
    dim3 gg((NN + 127) / 128, 2);
    kGemmMMA<<<gg, 256>>>(W2, al2, ar2);
    kNode<<<NN, 256>>>(1, b2, gids, Ww, bw);
    kH<<<GG, 128>>>(Wp1, bp1, gamma, beta, rm, rv, Wp2, bp2, outp);
}

// round 11
// speedup vs baseline: 2.1273x; 1.2309x over previous
#include <cuda_runtime.h>
#include <math.h>
#include <stdint.h>

#define NN   50000
#define EE   800000
#define IN_F 30
#define HH   8
#define DD   32
#define GG   512
#define HIDN 128
#define F1   256            // H*D

// ---------------- device scratch (no allocation allowed) ----------------
__device__ float g_feat1[NN * F1];
__device__ float g_out1 [NN * F1];   // layer-1 seed: x@resW1 + b1
__device__ float g_h1   [NN * F1];
__device__ float g_feat2[NN * F1];
__device__ float g_el1[NN * HH], g_er1[NN * HH];
__device__ float g_el2[NN * HH], g_er2[NN * HH];
__device__ float g_gsum[GG * DD], g_gmax[GG * DD];
// CSR-by-dst
__device__ int g_cnt[NN];
__device__ int g_rowptr[NN + 1];
__device__ int g_cursor[NN];
__device__ int g_csrc[EE];

__device__ __forceinline__ void atomicMaxF(float* addr, float v) {
    if (v >= 0.0f) atomicMax((int*)addr, __float_as_int(v));
    else           atomicMin((unsigned int*)addr, __float_as_uint(v));
}

__device__ __forceinline__ uint32_t f2tf32(float f) {
    uint32_t r;
    asm("cvt.rna.tf32.f32 %0, %1;" : "=r"(r) : "f"(f));
    return r;
}

__device__ __forceinline__ void mma_tf32(float* c, const uint32_t* a, const uint32_t* b) {
    asm volatile(
        "mma.sync.aligned.m16n8k8.row.col.f32.tf32.tf32.f32 "
        "{%0,%1,%2,%3}, {%4,%5,%6,%7}, {%8,%9}, {%0,%1,%2,%3};"
        : "+f"(c[0]), "+f"(c[1]), "+f"(c[2]), "+f"(c[3])
        : "r"(a[0]), "r"(a[1]), "r"(a[2]), "r"(a[3]), "r"(b[0]), "r"(b[1]));
}

// ---------------- Stage A: layer-1 projection + attention dots + inits ----
__global__ void __launch_bounds__(256) kA(
    const float* __restrict__ x, const float* __restrict__ W1,
    const float* __restrict__ resW1, const float* __restrict__ b1,
    const float* __restrict__ al1, const float* __restrict__ ar1)
{
    int n = blockIdx.x;
    int t = threadIdx.x;
    __shared__ float xs[IN_F];
    if (t < IN_F) xs[t] = x[n * IN_F + t];
    if (t == 0) g_cnt[n] = 0;
    __syncthreads();

    float f = 0.f, r = 0.f;
#pragma unroll
    for (int k = 0; k < IN_F; k++) {
        float xv = xs[k];
        f += xv * W1[k * F1 + t];
        r += xv * resW1[k * F1 + t];
    }
    g_feat1[n * F1 + t] = f;
    g_out1[n * F1 + t]  = r + b1[t];

    int h = t >> 5, lane = t & 31;
    float elv = f * al1[h * DD + lane];
    float erv = f * ar1[h * DD + lane];
#pragma unroll
    for (int o = 16; o > 0; o >>= 1) {
        elv += __shfl_down_sync(0xffffffffu, elv, o);
        erv += __shfl_down_sync(0xffffffffu, erv, o);
    }
    if (lane == 0) { g_el1[n * HH + h] = elv; g_er1[n * HH + h] = erv; }

    int gid = n * F1 + t;
    if (gid < GG * DD) { g_gsum[gid] = 0.f; g_gmax[gid] = -INFINITY; }
}

// ---------------- CSR build: histogram ------------------------------------
__global__ void __launch_bounds__(256) kHist(const int* __restrict__ dst)
{
    int e = blockIdx.x * 256 + threadIdx.x;
    if (e < EE) atomicAdd(&g_cnt[dst[e]], 1);
}

// ---------------- CSR build: single-block exclusive scan ------------------
__global__ void __launch_bounds__(1024) kScan()
{
    __shared__ int warpsum[32];
    __shared__ int s_run;
    int t = threadIdx.x, lane = t & 31, wid = t >> 5;
    if (t == 0) s_run = 0;
    __syncthreads();
    for (int base = 0; base < NN; base += 1024) {
        int idx = base + t;
        int v = (idx < NN) ? g_cnt[idx] : 0;
        int x = v;
#pragma unroll
        for (int o = 1; o < 32; o <<= 1) {
            int y = __shfl_up_sync(0xffffffffu, x, o);
            if (lane >= o) x += y;
        }
        if (lane == 31) warpsum[wid] = x;
        __syncthreads();
        if (wid == 0) {
            int y = warpsum[lane];
#pragma unroll
            for (int o = 1; o < 32; o <<= 1) {
                int z = __shfl_up_sync(0xffffffffu, y, o);
                if (lane >= o) y += z;
            }
            warpsum[lane] = y;
        }
        __syncthreads();
        int excl = x - v + (wid > 0 ? warpsum[wid - 1] : 0) + s_run;
        if (idx < NN) { g_rowptr[idx] = excl; g_cursor[idx] = excl; }
        __syncthreads();
        if (t == 0) s_run += warpsum[31];
        __syncthreads();
    }
    if (t == 0) g_rowptr[NN] = s_run;
}

// ---------------- CSR build: scatter src by dst ---------------------------
__global__ void __launch_bounds__(256) kScatter(
    const int* __restrict__ src, const int* __restrict__ dst)
{
    int e = blockIdx.x * 256 + threadIdx.x;
    if (e >= EE) return;
    int pos = atomicAdd(&g_cursor[dst[e]], 1);
    g_csrc[pos] = src[e];
}

// ---------------- Warp-per-node fused GAT layer (no syncs) ----------------
// lane owns float4 chunks c0=lane (feats 4L..4L+3, head L>>3) and
// c1=lane+32 (feats 128+4L.., head 4+(L>>3)).
__global__ void __launch_bounds__(256) kNodeW(
    int layer, const float* __restrict__ b2,
    const int* __restrict__ gids, const float* __restrict__ Ww,
    const float* __restrict__ bw)
{
    int n = blockIdx.x * 8 + (threadIdx.x >> 5);
    if (n >= NN) return;
    int lane = threadIdx.x & 31;

    const float* feat = layer ? g_feat2 : g_feat1;
    const float* el   = layer ? g_el2   : g_el1;
    const float* er   = layer ? g_er2   : g_er1;

    int r0  = g_rowptr[n];
    int deg = g_rowptr[n + 1] - r0;

    float er_l = (lane < 8) ? er[n * HH + lane] : 0.f;
    float ssum = 0.f;
    int h0 = lane >> 3, h1 = 4 + (lane >> 3);

    float4 a0 = make_float4(0.f, 0.f, 0.f, 0.f);
    float4 a1 = make_float4(0.f, 0.f, 0.f, 0.f);

    for (int base = 0; base < deg; base += 32) {
        int cnt = min(32, deg - base);
        int sj_l = (lane < cnt) ? g_csrc[r0 + base + lane] : 0;
#pragma unroll 4
        for (int j = 0; j < cnt; j++) {
            int sj = __shfl_sync(0xffffffffu, sj_l, j);
            float ev = 0.f;
            if (lane < 8) {
                float e = el[sj * HH + lane] + er_l;
                e = e > 0.f ? e : 0.2f * e;
                ev = __expf(e);
                ssum += ev;
            }
            float w0 = __shfl_sync(0xffffffffu, ev, h0);
            float w1 = __shfl_sync(0xffffffffu, ev, h1);
            const float4* fp = (const float4*)(feat + (size_t)sj * F1);
            float4 f0 = fp[lane];
            float4 f1 = fp[lane + 32];
            a0.x += w0 * f0.x; a0.y += w0 * f0.y;
            a0.z += w0 * f0.z; a0.w += w0 * f0.w;
            a1.x += w1 * f1.x; a1.y += w1 * f1.y;
            a1.z += w1 * f1.z; a1.w += w1 * f1.w;
        }
    }

    float invs = (lane < 8) ? (1.f / fmaxf(ssum, 1e-9f)) : 0.f;
    float i0 = __shfl_sync(0xffffffffu, invs, h0);
    float i1 = __shfl_sync(0xffffffffu, invs, h1);

    if (layer == 0) {
        const float4* sp = (const float4*)(g_out1 + (size_t)n * F1);
        float4 s0 = sp[lane], s1 = sp[lane + 32];
        float4 o0, o1;
        o0.x = s0.x + a0.x * i0; o0.y = s0.y + a0.y * i0;
        o0.z = s0.z + a0.z * i0; o0.w = s0.w + a0.w * i0;
        o1.x = s1.x + a1.x * i1; o1.y = s1.y + a1.y * i1;
        o1.z = s1.z + a1.z * i1; o1.w = s1.w + a1.w * i1;
        o0.x = o0.x > 0.f ? o0.x : expm1f(o0.x);
        o0.y = o0.y > 0.f ? o0.y : expm1f(o0.y);
        o0.z = o0.z > 0.f ? o0.z : expm1f(o0.z);
        o0.w = o0.w > 0.f ? o0.w : expm1f(o0.w);
        o1.x = o1.x > 0.f ? o1.x : expm1f(o1.x);
        o1.y = o1.y > 0.f ? o1.y : expm1f(o1.y);
        o1.z = o1.z > 0.f ? o1.z : expm1f(o1.z);
        o1.w = o1.w > 0.f ? o1.w : expm1f(o1.w);
        float4* dp = (float4*)(g_h1 + (size_t)n * F1);
        dp[lane] = o0; dp[lane + 32] = o1;
    } else {
        // seed = b2 + h1; out = seed + acc*inv; then head-mean + gate + readout
        const float4* bp = (const float4*)b2;
        const float4* hp = (const float4*)(g_h1 + (size_t)n * F1);
        float4 b0 = bp[lane], b1v = bp[lane + 32];
        float4 hh0 = hp[lane], hh1 = hp[lane + 32];
        float4 o0, o1;
        o0.x = b0.x + hh0.x + a0.x * i0; o0.y = b0.y + hh0.y + a0.y * i0;
        o0.z = b0.z + hh0.z + a0.z * i0; o0.w = b0.w + hh0.w + a0.w * i0;
        o1.x = b1v.x + hh1.x + a1.x * i1; o1.y = b1v.y + hh1.y + a1.y * i1;
        o1.z = b1v.z + hh1.z + a1.z * i1; o1.w = b1v.w + hh1.w + a1.w * i1;
        // sum heads: lane L covers heads {L>>3, 4+(L>>3)} for d=4(L&7)..+3
        float4 s2;
        s2.x = o0.x + o1.x; s2.y = o0.y + o1.y;
        s2.z = o0.z + o1.z; s2.w = o0.w + o1.w;
#pragma unroll
        for (int off = 8; off <= 16; off <<= 1) {
            s2.x += __shfl_xor_sync(0xffffffffu, s2.x, off);
            s2.y += __shfl_xor_sync(0xffffffffu, s2.y, off);
            s2.z += __shfl_xor_sync(0xffffffffu, s2.z, off);
            s2.w += __shfl_xor_sync(0xffffffffu, s2.w, off);
        }
        float4 h2;
        h2.x = s2.x * 0.125f + 0.0f; h2.y = s2.y * 0.125f + 0.0f;
        h2.z = s2.z * 0.125f + 0.0f; h2.w = s2.w * 0.125f + 0.0f;
        int d0 = 4 * (lane & 7);
        float part = 0.f;
        if (lane < 8)
            part = h2.x * Ww[d0] + h2.y * Ww[d0 + 1]
                 + h2.z * Ww[d0 + 2] + h2.w * Ww[d0 + 3];
#pragma unroll
        for (int off = 16; off > 0; off >>= 1)
            part += __shfl_xor_sync(0xffffffffu, part, off);
        float w = 1.f / (1.f + __expf(-(part + bw[0])));
        if (lane < 8) {
            int g = gids[n];
            float* gsp = &g_gsum[g * DD + d0];
            atomicAdd(gsp + 0, w * h2.x);
            atomicAdd(gsp + 1, w * h2.y);
            atomicAdd(gsp + 2, w * h2.z);
            atomicAdd(gsp + 3, w * h2.w);
            float* gmp = &g_gmax[g * DD + d0];
            atomicMaxF(gmp + 0, h2.x);
            atomicMaxF(gmp + 1, h2.y);
            atomicMaxF(gmp + 2, h2.z);
            atomicMaxF(gmp + 3, h2.w);
        }
    }
}

// ---------------- tf32 mma.sync GEMM: feat2 = h1 @ W2, fused el2/er2 ------
#define AS_STRIDE 36
#define BS_STRIDE 136
__global__ void __launch_bounds__(256) kGemmMMA(
    const float* __restrict__ W2,
    const float* __restrict__ al2, const float* __restrict__ ar2)
{
    __shared__ uint32_t as_[128 * AS_STRIDE];
    __shared__ uint32_t bs_[32 * BS_STRIDE];
    __shared__ float sal[128], sar[128];

    int t = threadIdx.x;
    int lane = t & 31, warp = t >> 5;
    int gid = lane >> 2, tid4 = lane & 3;
    int wm = warp >> 1, wn = warp & 1;

    int row0 = blockIdx.x * 128;
    int c0   = blockIdx.y * 128;

    if (t < 128) { sal[t] = al2[c0 + t]; sar[t] = ar2[c0 + t]; }

    float acc[2][8][4];
#pragma unroll
    for (int i = 0; i < 2; i++)
#pragma unroll
        for (int j = 0; j < 8; j++)
#pragma unroll
            for (int q = 0; q < 4; q++) acc[i][j][q] = 0.f;

    for (int s = 0; s < 8; s++) {
#pragma unroll
        for (int q = 0; q < 4; q++) {
            int p = t + q * 256;
            int r = p >> 3, c4 = p & 7;
            float4 v = (row0 + r < NN)
                ? *(const float4*)(g_h1 + (size_t)(row0 + r) * F1 + s * 32 + c4 * 4)
                : make_float4(0.f, 0.f, 0.f, 0.f);
            uint32_t* dstp = &as_[r * AS_STRIDE + c4 * 4];
            dstp[0] = f2tf32(v.x); dstp[1] = f2tf32(v.y);
            dstp[2] = f2tf32(v.z); dstp[3] = f2tf32(v.w);
        }
#pragma unroll
        for (int q = 0; q < 4; q++) {
            int p = t + q * 256;
            int r = p >> 5, c4 = p & 31;
            float4 v = *(const float4*)(W2 + (size_t)(s * 32 + r) * F1 + c0 + c4 * 4);
            uint32_t* dstp = &bs_[r * BS_STRIDE + c4 * 4];
            dstp[0] = f2tf32(v.x); dstp[1] = f2tf32(v.y);
            dstp[2] = f2tf32(v.z); dstp[3] = f2tf32(v.w);
        }
        __syncthreads();

#pragma unroll
        for (int kk = 0; kk < 4; kk++) {
            uint32_t bf[8][2];
            int kb = kk * 8 + tid4;
#pragma unroll
            for (int j = 0; j < 8; j++) {
                int nn = wn * 64 + j * 8 + gid;
                bf[j][0] = bs_[kb * BS_STRIDE + nn];
                bf[j][1] = bs_[(kb + 4) * BS_STRIDE + nn];
            }
#pragma unroll
            for (int i = 0; i < 2; i++) {
                uint32_t af[4];
                int m = wm * 32 + i * 16 + gid;
                af[0] = as_[m * AS_STRIDE + kk * 8 + tid4];
                af[1] = as_[(m + 8) * AS_STRIDE + kk * 8 + tid4];
                af[2] = as_[m * AS_STRIDE + kk * 8 + tid4 + 4];
                af[3] = as_[(m + 8) * AS_STRIDE + kk * 8 + tid4 + 4];
#pragma unroll
                for (int j = 0; j < 8; j++) mma_tf32(acc[i][j], af, bf[j]);
            }
        }
        __syncthreads();
    }

#pragma unroll
    for (int i = 0; i < 2; i++) {
        int mrow = row0 + wm * 32 + i * 16 + gid;
        float elv[2][2] = {{0.f, 0.f}, {0.f, 0.f}};
        float erv[2][2] = {{0.f, 0.f}, {0.f, 0.f}};
#pragma unroll
        for (int j = 0; j < 8; j++) {
            int nl = wn * 64 + j * 8 + tid4 * 2;
            int hl = j >> 2;
            float* cc = acc[i][j];
            float w0l = sal[nl], w1l = sal[nl + 1];
            float w0r = sar[nl], w1r = sar[nl + 1];
            if (mrow < NN)
                *(float2*)(g_feat2 + (size_t)mrow * F1 + c0 + nl) =
                    make_float2(cc[0], cc[1]);
            if (mrow + 8 < NN)
                *(float2*)(g_feat2 + (size_t)(mrow + 8) * F1 + c0 + nl) =
                    make_float2(cc[2], cc[3]);
            elv[0][hl] += cc[0] * w0l + cc[1] * w1l;
            elv[1][hl] += cc[2] * w0l + cc[3] * w1l;
            erv[0][hl] += cc[0] * w0r + cc[1] * w1r;
            erv[1][hl] += cc[2] * w0r + cc[3] * w1r;
        }
#pragma unroll
        for (int off = 1; off < 4; off <<= 1) {
#pragma unroll
            for (int rh = 0; rh < 2; rh++)
#pragma unroll
                for (int hl = 0; hl < 2; hl++) {
                    elv[rh][hl] += __shfl_xor_sync(0xffffffffu, elv[rh][hl], off);
                    erv[rh][hl] += __shfl_xor_sync(0xffffffffu, erv[rh][hl], off);
                }
        }
        if (tid4 == 0) {
            int hbase = (c0 >> 5) + wn * 2;
            if (mrow < NN) {
                g_el2[mrow * HH + hbase]     = elv[0][0];
                g_el2[mrow * HH + hbase + 1] = elv[0][1];
                g_er2[mrow * HH + hbase]     = erv[0][0];
                g_er2[mrow * HH + hbase + 1] = erv[0][1];
            }
            if (mrow + 8 < NN) {
                g_el2[(mrow + 8) * HH + hbase]     = elv[1][0];
                g_el2[(mrow + 8) * HH + hbase + 1] = elv[1][1];
                g_er2[(mrow + 8) * HH + hbase]     = erv[1][0];
                g_er2[(mrow + 8) * HH + hbase + 1] = erv[1][1];
            }
        }
    }
}

// ---------------- Stage H: MLP predictor ----------------------------------
__global__ void __launch_bounds__(128) kH(
    const float* __restrict__ Wp1, const float* __restrict__ bp1,
    const float* __restrict__ gamma, const float* __restrict__ beta,
    const float* __restrict__ rm, const float* __restrict__ rv,
    const float* __restrict__ Wp2, const float* __restrict__ bp2,
    float* __restrict__ outp)
{
    int g = blockIdx.x, t = threadIdx.x;
    __shared__ float gs[64];
    __shared__ float wsum[4];
    if (t < 32) gs[t] = g_gsum[g * DD + t];
    else if (t < 64) {
        float mv = g_gmax[g * DD + (t - 32)];
        if (!isfinite(mv)) mv = 0.f;
        gs[t] = mv;
    }
    __syncthreads();
    float acc = bp1[t];
#pragma unroll
    for (int k = 0; k < 64; k++) acc += gs[k] * Wp1[k * HIDN + t];
    acc = fmaxf(acc, 0.f);
    acc = (acc - rm[t]) * rsqrtf(rv[t] + 1e-5f) * gamma[t] + beta[t];
    float v = acc * Wp2[t];
#pragma unroll
    for (int o = 16; o > 0; o >>= 1) v += __shfl_xor_sync(0xffffffffu, v, o);
    if ((t & 31) == 0) wsum[t >> 5] = v;
    __syncthreads();
    if (t == 0) outp[g] = wsum[0] + wsum[1] + wsum[2] + wsum[3] + bp2[0];
}

// ---------------- launcher ------------------------------------------------
extern "C" void kernel_launch(void* const* d_in, const int* in_sizes, int n_in,
                              void* d_out, int out_size)
{
    const float* x     = (const float*)d_in[0];
    const int*   src   = (const int*)  d_in[1];
    const int*   dst   = (const int*)  d_in[2];
    const int*   gids  = (const int*)  d_in[3];
    const float* W1    = (const float*)d_in[4];
    const float* al1   = (const float*)d_in[5];
    const float* ar1   = (const float*)d_in[6];
    const float* b1    = (const float*)d_in[7];
    const float* resW1 = (const float*)d_in[8];
    const float* W2    = (const float*)d_in[9];
    const float* al2   = (const float*)d_in[10];
    const float* ar2   = (const float*)d_in[11];
    const float* b2    = (const float*)d_in[12];
    const float* Ww    = (const float*)d_in[13];
    const float* bw    = (const float*)d_in[14];
    const float* Wp1   = (const float*)d_in[15];
    const float* bp1   = (const float*)d_in[16];
    const float* gamma = (const float*)d_in[17];
    const float* beta  = (const float*)d_in[18];
    const float* rm    = (const float*)d_in[19];
    const float* rv    = (const float*)d_in[20];
    const float* Wp2   = (const float*)d_in[21];
    const float* bp2   = (const float*)d_in[22];
    float* outp = (float*)d_out;

    int eb = (EE + 255) / 256;

    kA<<<NN, 256>>>(x, W1, resW1, b1, al1, ar1);
    kHist<<<eb, 256>>>(dst);
    kScan<<<1, 1024>>>();
    kScatter<<<eb, 256>>>(src, dst);
    kNodeW<<<(NN + 7) / 8, 256>>>(0, b2, gids, Ww, bw);
    dim3 gg((NN + 127) / 128, 2);
    kGemmMMA<<<gg, 256>>>(W2, al2, ar2);
    kNodeW<<<(NN + 7) / 8, 256>>>(1, b2, gids, Ww, bw);
    kH<<<GG, 128>>>(Wp1, bp1, gamma, beta, rm, rv, Wp2, bp2, outp);
}